// round 13
// baseline (speedup 1.0000x reference)
#include <cuda_runtime.h>
#include <cuda_bf16.h>
#include <cstdint>

#define ITERS 3
#define EPSc 1e-8f
#define LN_EPSc 1e-5f
#define Mc 262144   // B*N
#define BSc 512     // B*S

// ---------------- scratch (device globals) ----------------------------------
__device__ __nv_bfloat16 g_a2 [67108864]; // [M,256] bf16 of LN(x)
__device__ __nv_bfloat16 g_wb2[131072];   // [512 n][256 k] bf16 K-major
__device__ __nv_bfloat16 g_kbufh[67108864];// K [B,H,N,DH] bf16
__device__ __nv_bfloat16 g_vbufh[67108864];// V [B,H,N,DH] bf16
__device__ float g_slots[131072];
__device__ float g_q    [131072];
__device__ float g_upd2 [131072];
__device__ float g_h1   [131072];
__device__ float g_xg   [393216];
__device__ float g_hg   [393216];
__device__ float g_updpart[524288];        // [bh*4+chunk][8s][32dh]
__device__ float g_rspart [16384];         // [bh*4+chunk][8s]

__device__ __forceinline__ uint32_t smem_u32(const void* p) {
    uint32_t a;
    asm("{ .reg .u64 t; cvta.to.shared.u64 t, %1; cvt.u32.u64 %0, t; }" : "=r"(a) : "l"(p));
    return a;
}
__device__ __forceinline__ void cp_async16(uint32_t ds, const void* gp) {
    asm volatile("cp.async.cg.shared.global [%0], [%1], 16;" :: "r"(ds), "l"(gp));
}
#define CP_COMMIT() asm volatile("cp.async.commit_group;")
#define CP_WAIT1()  asm volatile("cp.async.wait_group 1;")
#define CP_WAIT0()  asm volatile("cp.async.wait_group 0;")
#define LDMX4(r0,r1,r2,r3,a) \
    asm volatile("ldmatrix.sync.aligned.m8n8.x4.shared.b16 {%0,%1,%2,%3}, [%4];" \
        : "=r"(r0),"=r"(r1),"=r"(r2),"=r"(r3) : "r"(a))
#define MMA16816(acc, a0,a1,a2,a3, b0,b1) \
    asm volatile("mma.sync.aligned.m16n8k16.row.col.f32.bf16.bf16.f32 " \
        "{%0,%1,%2,%3}, {%4,%5,%6,%7}, {%8,%9}, {%0,%1,%2,%3};" \
        : "+f"((acc)[0]), "+f"((acc)[1]), "+f"((acc)[2]), "+f"((acc)[3]) \
        : "r"(a0), "r"(a1), "r"(a2), "r"(a3), "r"(b0), "r"(b1))

// FMA-pipe exponential (no MUFU). Valid for |x| < ~80; rel err ~1.2e-7.
__device__ __forceinline__ float fexp(float x) {
    const float LOG2E = 1.4426950408889634f;
    const float MAGIC = 12582912.0f;          // 1.5 * 2^23
    float t  = fmaf(x, LOG2E, MAGIC);         // FFMA
    int   e  = __float_as_int(t) - 0x4B400000;// IADD: round(x*log2e)
    float fi = t - MAGIC;                     // FADD
    float f  = fmaf(x, LOG2E, -fi);           // FFMA: frac in [-0.5, 0.5]
    float u  = f * 0.6931471805599453f;       // FMUL
    float p  = 0.0013888889f;
    p = fmaf(p, u, 0.0083333333f);
    p = fmaf(p, u, 0.0416666667f);
    p = fmaf(p, u, 0.1666666667f);
    p = fmaf(p, u, 0.5f);
    p = fmaf(p, u, 1.0f);
    p = fmaf(p, u, 1.0f);
    return __int_as_float(__float_as_int(p) + (e << 23));
}

// ---------------- misc small kernels -----------------------------------------
__global__ void init_slots_kernel(const float* __restrict__ noise,
                                  const float* __restrict__ mean,
                                  const float* __restrict__ logv,
                                  float* __restrict__ slots)
{
    int idx = blockIdx.x * 256 + threadIdx.x;
    int d = idx & 255;
    slots[idx] = mean[d] + expf(logv[d]) * noise[idx];
}

// LN(inputs) -> bf16 [M,256]
__global__ void ln_kv_kernel(const float* __restrict__ src, __nv_bfloat16* __restrict__ dst,
                             const float* __restrict__ w, const float* __restrict__ b)
{
    int row = blockIdx.x * 8 + (threadIdx.x >> 5);
    int lane = threadIdx.x & 31;
    const float4* r4 = (const float4*)(src + (size_t)row * 256);
    float4 v0 = r4[lane], v1 = r4[lane + 32];
    float s  = v0.x + v0.y + v0.z + v0.w + v1.x + v1.y + v1.z + v1.w;
    float sq = v0.x*v0.x + v0.y*v0.y + v0.z*v0.z + v0.w*v0.w
             + v1.x*v1.x + v1.y*v1.y + v1.z*v1.z + v1.w*v1.w;
#pragma unroll
    for (int o = 16; o > 0; o >>= 1) {
        s  += __shfl_xor_sync(~0u, s,  o);
        sq += __shfl_xor_sync(~0u, sq, o);
    }
    float mean = s * (1.0f/256.0f);
    float rstd = rsqrtf(sq * (1.0f/256.0f) - mean*mean + LN_EPSc);
    float4 wa = ((const float4*)w)[lane], wb = ((const float4*)w)[lane+32];
    float4 ba = ((const float4*)b)[lane], bb = ((const float4*)b)[lane+32];
    float4 o0, o1;
    o0.x=(v0.x-mean)*rstd*wa.x+ba.x; o0.y=(v0.y-mean)*rstd*wa.y+ba.y;
    o0.z=(v0.z-mean)*rstd*wa.z+ba.z; o0.w=(v0.w-mean)*rstd*wa.w+ba.w;
    o1.x=(v1.x-mean)*rstd*wb.x+bb.x; o1.y=(v1.y-mean)*rstd*wb.y+bb.y;
    o1.z=(v1.z-mean)*rstd*wb.z+bb.z; o1.w=(v1.w-mean)*rstd*wb.w+bb.w;
    __nv_bfloat16* dr = dst + (size_t)row * 256;
    __nv_bfloat162 h0; h0.x = __float2bfloat16(o0.x); h0.y = __float2bfloat16(o0.y);
    __nv_bfloat162 h1; h1.x = __float2bfloat16(o0.z); h1.y = __float2bfloat16(o0.w);
    __nv_bfloat162 h2; h2.x = __float2bfloat16(o1.x); h2.y = __float2bfloat16(o1.y);
    __nv_bfloat162 h3; h3.x = __float2bfloat16(o1.z); h3.y = __float2bfloat16(o1.w);
    ((__nv_bfloat162*)(dr + lane*4))[0] = h0;
    ((__nv_bfloat162*)(dr + lane*4))[1] = h1;
    ((__nv_bfloat162*)(dr + 128 + lane*4))[0] = h2;
    ((__nv_bfloat162*)(dr + 128 + lane*4))[1] = h3;
}

// W -> [n][k] K-major bf16 (n<256: wk, else wv)
__global__ void prep_w_kernel(const float* __restrict__ wk, const float* __restrict__ wv,
                              __nv_bfloat16* __restrict__ B2)
{
    int n = blockIdx.x;
    int k = threadIdx.x;
    const float* W = (n < 256) ? wk : wv;
    B2[(size_t)n * 256 + k] = __float2bfloat16(W[(size_t)k * 256 + (n & 255)]);
}

// ---------------- K/V GEMM: pure bf16, 4 chunks of K=64 ----------------------
#define KV_SMEM (32768 * 2)
__global__ __launch_bounds__(256, 2)
void kv_gemm_mma(const __nv_bfloat16* __restrict__ A2, const __nv_bfloat16* __restrict__ B2,
                 const float* __restrict__ bk, const float* __restrict__ bv,
                 __nv_bfloat16* __restrict__ Kout, __nv_bfloat16* __restrict__ Vout)
{
    extern __shared__ char dsm[];
    uint32_t sbase = smem_u32(dsm);
    int tid = threadIdx.x, lane = tid & 31, wid = tid >> 5;
    int warp_m = wid & 1, warp_n = wid >> 1;
    int cb  = blockIdx.x;
    int m0  = blockIdx.y * 128;
    int mat = cb >> 1, nh = cb & 1;
    const float* bias = mat ? bv : bk;
    __nv_bfloat16* Out = mat ? Vout : Kout;

    float acc[4][4][4];
#pragma unroll
    for (int a = 0; a < 4; ++a)
#pragma unroll
        for (int b = 0; b < 4; ++b)
#pragma unroll
            for (int r = 0; r < 4; ++r) acc[a][b][r] = 0.0f;

    int lr = tid >> 3, lj = tid & 7;
    int brow_g = mat * 256 + nh * 128;

    int l7 = lane & 7, l15 = lane & 15, lhA = lane >> 4;
    int nrow_loc = (lane >> 4) * 8 + l7, hB = (lane >> 3) & 1;
    uint32_t aRow[4], bRow[2];
#pragma unroll
    for (int mt = 0; mt < 4; ++mt) aRow[mt] = (uint32_t)(warp_m*64 + mt*16 + l15) << 7;
#pragma unroll
    for (int g = 0; g < 2; ++g) bRow[g] = (uint32_t)(warp_n*32 + g*16 + nrow_loc) << 7;

#define LOAD_CHUNK(c, stg) do {                                               \
    uint32_t sa = sbase + (stg)*32768;                                        \
    int ko = (c)*64;                                                          \
    _Pragma("unroll")                                                         \
    for (int i = 0; i < 4; ++i) {                                             \
        int r = lr + i*32;                                                    \
        uint32_t so = (r<<7) + ((lj ^ (r&7))<<4);                             \
        cp_async16(sa + so, A2 + (size_t)(m0 + r)*256 + ko + lj*8);           \
        cp_async16(sa + 16384 + so, B2 + (size_t)(brow_g + r)*256 + ko + lj*8);\
    }                                                                         \
    CP_COMMIT();                                                              \
} while (0)

    LOAD_CHUNK(0, 0);
    LOAD_CHUNK(1, 1);

    for (int c = 0; c < 4; ++c) {
        if (c == 3) { CP_WAIT0(); } else { CP_WAIT1(); }
        __syncthreads();
        uint32_t sa = sbase + (c & 1) * 32768;
#pragma unroll
        for (int ks = 0; ks < 4; ++ks) {
            uint32_t achk = (uint32_t)(((2*ks + lhA) ^ l7) << 4);
            uint32_t bchk = (uint32_t)(((2*ks + hB)  ^ l7) << 4);
            uint32_t af[4][4], bf[2][4];
#pragma unroll
            for (int mt = 0; mt < 4; ++mt)
                LDMX4(af[mt][0], af[mt][1], af[mt][2], af[mt][3], sa + aRow[mt] + achk);
#pragma unroll
            for (int g = 0; g < 2; ++g)
                LDMX4(bf[g][0], bf[g][1], bf[g][2], bf[g][3], sa + 16384 + bRow[g] + bchk);
#pragma unroll
            for (int mt = 0; mt < 4; ++mt)
#pragma unroll
                for (int nt = 0; nt < 4; ++nt)
                    MMA16816(acc[mt][nt], af[mt][0], af[mt][1], af[mt][2], af[mt][3],
                             bf[nt>>1][(nt&1)*2], bf[nt>>1][(nt&1)*2+1]);
        }
        __syncthreads();
        if (c + 2 < 4) LOAD_CHUNK(c + 2, c & 1);
    }

    int col_base = nh * 128 + warp_n * 32;
    int h = col_base >> 5;
#pragma unroll
    for (int mt = 0; mt < 4; ++mt) {
#pragma unroll
        for (int half = 0; half < 2; ++half) {
            int m = m0 + warp_m * 64 + mt * 16 + (lane >> 2) + half * 8;
            int bi = m >> 12, nn = m & 4095;
            __nv_bfloat16* dst = Out + ((size_t)(bi * 8 + h) * 4096 + nn) * 32;
#pragma unroll
            for (int nt = 0; nt < 4; ++nt) {
                int dh = nt * 8 + (lane & 3) * 2;
                __nv_bfloat162 o;
                o.x = __float2bfloat16(acc[mt][nt][half*2+0] + bias[col_base + dh]);
                o.y = __float2bfloat16(acc[mt][nt][half*2+1] + bias[col_base + dh + 1]);
                *(__nv_bfloat162*)(dst + dh) = o;
            }
        }
    }
#undef LOAD_CHUNK
}

// ---------------- small GEMM (512 rows), optional fused input-LN -------------
// modes: 0 plain, 1 relu, 2 residual add, 3 q-layout remap,
//        4 virtual-A: A = (sum_c upd_part[c]) * inv_rs (resid = rs_part)
__global__ __launch_bounds__(256)
void gemm512_kernel(const float* __restrict__ Ain, const float* __restrict__ Win,
                    const float* __restrict__ biasin, float* __restrict__ outin,
                    int Ncols, int mode, const float* __restrict__ resid,
                    const float* __restrict__ lnw, const float* __restrict__ lnb,
                    const float* __restrict__ A2, const float* __restrict__ W2,
                    const float* __restrict__ bias2, float* __restrict__ out2,
                    int y2)
{
    __shared__ float As[64][36];
    __shared__ float Bs[64][68];
    __shared__ float s_mean[32], s_rstd[32];
    __shared__ float s_inv[256];
    int tid = threadIdx.x, tx = tid & 31, ty = tid >> 5;
    int c0 = tx*2, r0 = ty*4;
    int m0 = blockIdx.x * 32;
    int yb = blockIdx.y;
    const float* A = Ain; const float* W = Win; const float* bias = biasin;
    float* out = outin;
    if (yb >= y2) { A = A2; W = W2; bias = bias2; out = out2; yb -= y2; }
    int n0 = yb * 64;
    int do_ln = (lnw != nullptr);

    if (do_ln) {
        int r = ty * 4 + (tx >> 3);
        const float4* rp = (const float4*)(A + (size_t)(m0 + r) * 256);
        float s = 0.0f, sq = 0.0f;
        for (int j = (tx & 7); j < 64; j += 8) {
            float4 v = rp[j];
            s  += v.x + v.y + v.z + v.w;
            sq += v.x*v.x + v.y*v.y + v.z*v.z + v.w*v.w;
        }
#pragma unroll
        for (int o = 4; o > 0; o >>= 1) {
            s  += __shfl_xor_sync(~0u, s,  o);
            sq += __shfl_xor_sync(~0u, sq, o);
        }
        if ((tx & 7) == 0) {
            float mean = s * (1.0f/256.0f);
            s_mean[r] = mean;
            s_rstd[r] = rsqrtf(sq * (1.0f/256.0f) - mean*mean + LN_EPSc);
        }
    }
    if (mode == 4) {
        int r = tid >> 3, hh = tid & 7;
        int m = m0 + r, b = m >> 3, s = m & 7;
        int bh = b * 8 + hh;
        float t = resid[(size_t)(bh*4+0)*8 + s] + resid[(size_t)(bh*4+1)*8 + s]
                + resid[(size_t)(bh*4+2)*8 + s] + resid[(size_t)(bh*4+3)*8 + s];
        s_inv[r*8 + hh] = 1.0f / fmaxf(t, 1e-12f);
    }
    __syncthreads();

    float acc[4][2] = {};
    for (int kt = 0; kt < 4; ++kt) {
        __syncthreads();
#pragma unroll
        for (int i = 0; i < 2; ++i) {
            int fid = tid*2 + i, ar = fid >> 4, kq = fid & 15;
            float4 va;
            if (mode == 4) {
                int m = m0 + ar, b = m >> 3, s = m & 7;
                int c = kt*64 + kq*4;
                int h = c >> 5, cc = c & 31;
                size_t base = ((size_t)(b*8 + h) * 4) * 256 + s*32 + cc;
                float4 v0 = *(const float4*)(A + base);
                float4 v1 = *(const float4*)(A + base + 256);
                float4 v2 = *(const float4*)(A + base + 512);
                float4 v3 = *(const float4*)(A + base + 768);
                float iv = s_inv[ar*8 + h];
                va.x = (v0.x+v1.x+v2.x+v3.x)*iv;
                va.y = (v0.y+v1.y+v2.y+v3.y)*iv;
                va.z = (v0.z+v1.z+v2.z+v3.z)*iv;
                va.w = (v0.w+v1.w+v2.w+v3.w)*iv;
            } else {
                va = *(const float4*)(A + (size_t)(m0+ar)*256 + kt*64 + kq*4);
                if (do_ln) {
                    float mn = s_mean[ar], rs = s_rstd[ar];
                    float4 lw = *(const float4*)(lnw + kt*64 + kq*4);
                    float4 lb = *(const float4*)(lnb + kt*64 + kq*4);
                    va.x = (va.x - mn)*rs*lw.x + lb.x;
                    va.y = (va.y - mn)*rs*lw.y + lb.y;
                    va.z = (va.z - mn)*rs*lw.z + lb.z;
                    va.w = (va.w - mn)*rs*lw.w + lb.w;
                }
            }
            As[kq*4+0][ar]=va.x; As[kq*4+1][ar]=va.y; As[kq*4+2][ar]=va.z; As[kq*4+3][ar]=va.w;
        }
#pragma unroll
        for (int j = 0; j < 4; ++j) {
            int fid = tid + j*256, br = fid >> 4, c4 = fid & 15;
            *(float4*)&Bs[br][c4*4] = *(const float4*)(W + (size_t)(kt*64+br)*Ncols + n0 + c4*4);
        }
        __syncthreads();
#pragma unroll 8
        for (int k = 0; k < 64; ++k) {
            float4 a4 = *(const float4*)&As[k][r0];
            float2 b2 = *(const float2*)&Bs[k][c0];
            acc[0][0]+=a4.x*b2.x; acc[0][1]+=a4.x*b2.y;
            acc[1][0]+=a4.y*b2.x; acc[1][1]+=a4.y*b2.y;
            acc[2][0]+=a4.z*b2.x; acc[2][1]+=a4.z*b2.y;
            acc[3][0]+=a4.w*b2.x; acc[3][1]+=a4.w*b2.y;
        }
    }
#pragma unroll
    for (int i = 0; i < 4; ++i)
#pragma unroll
        for (int j = 0; j < 2; ++j) {
            int m = m0 + r0 + i, n = n0 + c0 + j;
            float v = acc[i][j] + bias[n];
            if (mode == 1)      out[(size_t)m*Ncols + n] = fmaxf(v, 0.0f);
            else if (mode == 2) out[(size_t)m*256 + n] = resid[(size_t)m*256 + n] + v;
            else if (mode == 3) {
                int bq = m >> 3, s = m & 7, h = n >> 5, dh = n & 31;
                out[((size_t)(bq*8 + h)*8 + s)*32 + dh] = v;
            }
            else                out[(size_t)m*Ncols + n] = v;  // modes 0, 4
        }
}

// ---------------- attention, n-chunked (4 chunks of 1024), K+V bf16 ----------
#define ATT_SMEM ((8192 + 256 + 64 + 2048) * sizeof(float))
__global__ __launch_bounds__(256)
void attention_part(const float* __restrict__ q, const __nv_bfloat16* __restrict__ Kh,
                    const __nv_bfloat16* __restrict__ Vh,
                    float* __restrict__ upd_part, float* __restrict__ rs_part,
                    float* __restrict__ attn_out, int write_attn)
{
    extern __shared__ float sm[];
    float* attn_s = sm;                   // [8][1024]
    float* q_s    = sm + 8192;            // [8][32]
    float* red    = sm + 8192 + 256;      // [8][8]
    float* red2   = sm + 8192 + 256 + 64; // [8 warps][8 s][32 dh]
    int bh = blockIdx.x, chunk = blockIdx.y;
    int tid = threadIdx.x, lane = tid & 31, wid = tid >> 5;
    int n0 = chunk * 1024;

    q_s[tid] = q[(size_t)bh*256 + tid] * 0.0625f;  // scale = D^-0.5 = 1/16
    __syncthreads();

    float rs[8] = {};
    const __nv_bfloat16* Kb = Kh + (size_t)bh * 4096 * 32;
    for (int it = 0; it < 4; ++it) {
        int nl = it*256 + tid;
        const __nv_bfloat16* kr = Kb + (size_t)(n0 + nl) * 32;
        float d[8] = {};
#pragma unroll
        for (int c4 = 0; c4 < 4; ++c4) {
            float4 raw = *(const float4*)(kr + c4*8);
            const __nv_bfloat162* kp = (const __nv_bfloat162*)&raw;
            float2 k0 = __bfloat1622float2(kp[0]);
            float2 k1 = __bfloat1622float2(kp[1]);
            float2 k2 = __bfloat1622float2(kp[2]);
            float2 k3 = __bfloat1622float2(kp[3]);
#pragma unroll
            for (int s = 0; s < 8; ++s) {
                float4 qa = *(const float4*)(q_s + s*32 + c4*8);
                float4 qb = *(const float4*)(q_s + s*32 + c4*8 + 4);
                d[s] += k0.x*qa.x + k0.y*qa.y + k1.x*qa.z + k1.y*qa.w
                      + k2.x*qb.x + k2.y*qb.y + k3.x*qb.z + k3.y*qb.w;
            }
        }
        float mx = d[0];
#pragma unroll
        for (int s = 1; s < 8; ++s) mx = fmaxf(mx, d[s]);
        float e[8], sum = 0.0f;
#pragma unroll
        for (int s = 0; s < 8; ++s) { e[s] = fexp(d[s]-mx); sum += e[s]; }
        float inv = __fdividef(1.0f, sum);
#pragma unroll
        for (int s = 0; s < 8; ++s) {
            float p = e[s]*inv + EPSc;
            attn_s[s*1024 + nl] = p;
            rs[s] += p;
        }
    }
#pragma unroll
    for (int s = 0; s < 8; ++s)
#pragma unroll
        for (int o = 16; o > 0; o >>= 1) rs[s] += __shfl_xor_sync(~0u, rs[s], o);
    if (lane == 0)
#pragma unroll
        for (int s = 0; s < 8; ++s) red[wid*8 + s] = rs[s];
    __syncthreads();
    if (tid < 8) {
        float t = 0.0f;
#pragma unroll
        for (int w = 0; w < 8; ++w) t += red[w*8 + tid];
        rs_part[(size_t)(bh*4 + chunk)*8 + tid] = t;
    }

    // pass2: warp w owns n-substripe [w*128, (w+1)*128) of this chunk
    {
        const __nv_bfloat16* Vb = Vh + (size_t)bh * 4096 * 32;
        float acc[8] = {};
        int nb = wid * 128;
        for (int nl = nb; nl < nb + 128; nl += 4) {
            float4 a[8];
#pragma unroll
            for (int s = 0; s < 8; ++s) a[s] = *(const float4*)(attn_s + s*1024 + nl);
            int n = n0 + nl;
            float v0 = __bfloat162float(Vb[(size_t)(n+0)*32 + lane]);
            float v1 = __bfloat162float(Vb[(size_t)(n+1)*32 + lane]);
            float v2 = __bfloat162float(Vb[(size_t)(n+2)*32 + lane]);
            float v3 = __bfloat162float(Vb[(size_t)(n+3)*32 + lane]);
#pragma unroll
            for (int s = 0; s < 8; ++s)
                acc[s] += a[s].x*v0 + a[s].y*v1 + a[s].z*v2 + a[s].w*v3;
        }
#pragma unroll
        for (int s = 0; s < 8; ++s) red2[(wid*8 + s)*32 + lane] = acc[s];
    }
    __syncthreads();
    {
        int s = tid >> 5, dh = tid & 31;
        float t = 0.0f;
#pragma unroll
        for (int w = 0; w < 8; ++w) t += red2[(w*8 + s)*32 + dh];
        upd_part[(size_t)(bh*4 + chunk)*256 + s*32 + dh] = t;
    }

    if (write_attn) {  // unnormalized p; scaled later by attn_scale
        float* ao = attn_out + (size_t)bh * 32768 + n0;
        for (int i = tid; i < 8192; i += 256)
            ao[(i >> 10) * 4096 + (i & 1023)] = attn_s[i];
    }
}

__global__ void attn_scale(float* __restrict__ ao, const float* __restrict__ rsp)
{
    int bh = blockIdx.x, tid = threadIdx.x;
    __shared__ float inv[8];
    if (tid < 8) {
        float t = 0.0f;
#pragma unroll
        for (int c = 0; c < 4; ++c) t += rsp[(size_t)(bh*4 + c)*8 + tid];
        inv[tid] = 1.0f / fmaxf(t, 1e-12f);
    }
    __syncthreads();
    float* p = ao + (size_t)bh * 32768;
    for (int i = tid; i < 32768; i += 256)
        p[i] *= inv[i >> 12];
}

__global__ void gru_combine_kernel(const float* __restrict__ xg,
                                   const float* __restrict__ hg,
                                   float* __restrict__ slots)
{
    int idx = blockIdx.x * 256 + threadIdx.x;
    int row = idx >> 8, c = idx & 255;
    const float* x = xg + (size_t)row * 768;
    const float* h = hg + (size_t)row * 768;
    float r = 1.0f / (1.0f + expf(-(x[c]     + h[c])));
    float z = 1.0f / (1.0f + expf(-(x[256+c] + h[256+c])));
    float n = tanhf(x[512+c] + r * h[512+c]);
    slots[idx] = (1.0f - z) * n + z * slots[idx];
}

// ---------------- launcher ----------------------------------------------------
extern "C" void kernel_launch(void* const* d_in, const int* in_sizes, int n_in,
                              void* d_out, int out_size)
{
    const float* inp   = (const float*)d_in[0];
    const float* noise = (const float*)d_in[1];
    const float* smean = (const float*)d_in[2];
    const float* slogv = (const float*)d_in[3];
    const float* wq = (const float*)d_in[4];  const float* bq = (const float*)d_in[5];
    const float* wk = (const float*)d_in[6];  const float* bk = (const float*)d_in[7];
    const float* wv = (const float*)d_in[8];  const float* bv = (const float*)d_in[9];
    const float* wo = (const float*)d_in[10]; const float* bo = (const float*)d_in[11];
    const float* w_ih = (const float*)d_in[12]; const float* b_ih = (const float*)d_in[13];
    const float* w_hh = (const float*)d_in[14]; const float* b_hh = (const float*)d_in[15];
    const float* w1 = (const float*)d_in[16]; const float* b1 = (const float*)d_in[17];
    const float* w2 = (const float*)d_in[18]; const float* b2 = (const float*)d_in[19];
    const float* lin_w = (const float*)d_in[20]; const float* lin_b = (const float*)d_in[21];
    const float* ls_w  = (const float*)d_in[22]; const float* ls_b  = (const float*)d_in[23];
    const float* lff_w = (const float*)d_in[24]; const float* lff_b = (const float*)d_in[25];

    float* out      = (float*)d_out;
    float* attn_out = out + 131072;

    __nv_bfloat16 *a2, *wb2, *kbh, *vbh;
    float *slots,*qb,*upd2,*h1,*xg,*hg,*updp,*rsp;
    cudaGetSymbolAddress((void**)&a2,   g_a2);
    cudaGetSymbolAddress((void**)&wb2,  g_wb2);
    cudaGetSymbolAddress((void**)&kbh,  g_kbufh);
    cudaGetSymbolAddress((void**)&vbh,  g_vbufh);
    cudaGetSymbolAddress((void**)&slots,g_slots);
    cudaGetSymbolAddress((void**)&qb,   g_q);
    cudaGetSymbolAddress((void**)&upd2, g_upd2);
    cudaGetSymbolAddress((void**)&h1,   g_h1);
    cudaGetSymbolAddress((void**)&xg,   g_xg);
    cudaGetSymbolAddress((void**)&hg,   g_hg);
    cudaGetSymbolAddress((void**)&updp, g_updpart);
    cudaGetSymbolAddress((void**)&rsp,  g_rspart);

    cudaFuncSetAttribute(attention_part,
                         cudaFuncAttributeMaxDynamicSharedMemorySize, (int)ATT_SMEM);
    cudaFuncSetAttribute(kv_gemm_mma,
                         cudaFuncAttributeMaxDynamicSharedMemorySize, KV_SMEM);

    init_slots_kernel<<<BSc, 256>>>(noise, smean, slogv, slots);
    prep_w_kernel<<<512, 256>>>(wk, wv, wb2);
    ln_kv_kernel<<<Mc/8, 256>>>(inp, a2, lin_w, lin_b);
    kv_gemm_mma<<<dim3(4, Mc/128), 256, KV_SMEM>>>(a2, wb2, bk, bv, kbh, vbh);

    for (int it = 0; it < ITERS; ++it) {
        int last = (it == ITERS - 1);
        // q = LN(slots) @ wq (LN fused), remap to [B,H,S,DH]
        gemm512_kernel<<<dim3(16, 4), 256>>>(slots, wq, bq, qb, 256, 3, nullptr,
                                             ls_w, ls_b, nullptr, nullptr, nullptr, nullptr, 9999);
        attention_part<<<dim3(512, 4), 256, ATT_SMEM>>>(qb, kbh, vbh, updp, rsp, attn_out, last);
        // upd2 = (normalized upd from parts) @ wo + bo   (finalize fused, mode 4)
        gemm512_kernel<<<dim3(16, 4), 256>>>(updp, wo, bo, upd2, 256, 4, rsp,
                                             nullptr, nullptr, nullptr, nullptr, nullptr, nullptr, 9999);
        gemm512_kernel<<<dim3(16, 24), 256>>>(upd2, w_ih, b_ih, xg, 768, 0, nullptr,
                                              nullptr, nullptr, slots, w_hh, b_hh, hg, 12);
        gru_combine_kernel<<<BSc, 256>>>(xg, hg, slots);
        gemm512_kernel<<<dim3(16, 4), 256>>>(slots, w1, b1, h1, 256, 1, nullptr,
                                             lff_w, lff_b, nullptr, nullptr, nullptr, nullptr, 9999);
        gemm512_kernel<<<dim3(16, 4), 256>>>(h1, w2, b2, last ? out : slots, 256, 2, slots,
                                             nullptr, nullptr, nullptr, nullptr, nullptr, nullptr, 9999);
        if (last) attn_scale<<<512, 256>>>(attn_out, rsp);
    }
}

// round 14
// speedup vs baseline: 1.1590x; 1.1590x over previous
#include <cuda_runtime.h>
#include <cuda_bf16.h>
#include <cstdint>

#define ITERS 3
#define EPSc 1e-8f
#define LN_EPSc 1e-5f
#define Mc 262144   // B*N
#define BSc 512     // B*S

// ---------------- scratch (device globals) ----------------------------------
__device__ __nv_bfloat16 g_a2 [67108864]; // [M,256] bf16 of LN(x)
__device__ __nv_bfloat16 g_wb2[131072];   // [512 n][256 k] bf16 K-major
__device__ __nv_bfloat16 g_kbufh[67108864];// K [B,H,N,DH] bf16
__device__ __nv_bfloat16 g_vbufh[67108864];// V [B,H,N,DH] bf16
__device__ float g_slots[131072];
__device__ float g_q    [131072];
__device__ float g_upd2 [131072];
__device__ float g_h1   [131072];
__device__ float g_xg   [393216];
__device__ float g_hg   [393216];
__device__ float g_updpart[524288];        // [bh*4+chunk][8s][32dh]
__device__ float g_rspart [16384];         // [bh*4+chunk][8s]

__device__ __forceinline__ uint32_t smem_u32(const void* p) {
    uint32_t a;
    asm("{ .reg .u64 t; cvta.to.shared.u64 t, %1; cvt.u32.u64 %0, t; }" : "=r"(a) : "l"(p));
    return a;
}
__device__ __forceinline__ void cp_async16(uint32_t ds, const void* gp) {
    asm volatile("cp.async.cg.shared.global [%0], [%1], 16;" :: "r"(ds), "l"(gp));
}
#define CP_COMMIT() asm volatile("cp.async.commit_group;")
#define CP_WAIT1()  asm volatile("cp.async.wait_group 1;")
#define CP_WAIT0()  asm volatile("cp.async.wait_group 0;")
#define LDMX4(r0,r1,r2,r3,a) \
    asm volatile("ldmatrix.sync.aligned.m8n8.x4.shared.b16 {%0,%1,%2,%3}, [%4];" \
        : "=r"(r0),"=r"(r1),"=r"(r2),"=r"(r3) : "r"(a))
#define MMA16816(acc, a0,a1,a2,a3, b0,b1) \
    asm volatile("mma.sync.aligned.m16n8k16.row.col.f32.bf16.bf16.f32 " \
        "{%0,%1,%2,%3}, {%4,%5,%6,%7}, {%8,%9}, {%0,%1,%2,%3};" \
        : "+f"((acc)[0]), "+f"((acc)[1]), "+f"((acc)[2]), "+f"((acc)[3]) \
        : "r"(a0), "r"(a1), "r"(a2), "r"(a3), "r"(b0), "r"(b1))

// ---------------- misc small kernels -----------------------------------------
__global__ void init_slots_kernel(const float* __restrict__ noise,
                                  const float* __restrict__ mean,
                                  const float* __restrict__ logv,
                                  float* __restrict__ slots)
{
    int idx = blockIdx.x * 256 + threadIdx.x;
    int d = idx & 255;
    slots[idx] = mean[d] + expf(logv[d]) * noise[idx];
}

// LN(inputs) -> bf16 [M,256]
__global__ void ln_kv_kernel(const float* __restrict__ src, __nv_bfloat16* __restrict__ dst,
                             const float* __restrict__ w, const float* __restrict__ b)
{
    int row = blockIdx.x * 8 + (threadIdx.x >> 5);
    int lane = threadIdx.x & 31;
    const float4* r4 = (const float4*)(src + (size_t)row * 256);
    float4 v0 = r4[lane], v1 = r4[lane + 32];
    float s  = v0.x + v0.y + v0.z + v0.w + v1.x + v1.y + v1.z + v1.w;
    float sq = v0.x*v0.x + v0.y*v0.y + v0.z*v0.z + v0.w*v0.w
             + v1.x*v1.x + v1.y*v1.y + v1.z*v1.z + v1.w*v1.w;
#pragma unroll
    for (int o = 16; o > 0; o >>= 1) {
        s  += __shfl_xor_sync(~0u, s,  o);
        sq += __shfl_xor_sync(~0u, sq, o);
    }
    float mean = s * (1.0f/256.0f);
    float rstd = rsqrtf(sq * (1.0f/256.0f) - mean*mean + LN_EPSc);
    float4 wa = ((const float4*)w)[lane], wb = ((const float4*)w)[lane+32];
    float4 ba = ((const float4*)b)[lane], bb = ((const float4*)b)[lane+32];
    float4 o0, o1;
    o0.x=(v0.x-mean)*rstd*wa.x+ba.x; o0.y=(v0.y-mean)*rstd*wa.y+ba.y;
    o0.z=(v0.z-mean)*rstd*wa.z+ba.z; o0.w=(v0.w-mean)*rstd*wa.w+ba.w;
    o1.x=(v1.x-mean)*rstd*wb.x+bb.x; o1.y=(v1.y-mean)*rstd*wb.y+bb.y;
    o1.z=(v1.z-mean)*rstd*wb.z+bb.z; o1.w=(v1.w-mean)*rstd*wb.w+bb.w;
    __nv_bfloat16* dr = dst + (size_t)row * 256;
    __nv_bfloat162 h0; h0.x = __float2bfloat16(o0.x); h0.y = __float2bfloat16(o0.y);
    __nv_bfloat162 h1; h1.x = __float2bfloat16(o0.z); h1.y = __float2bfloat16(o0.w);
    __nv_bfloat162 h2; h2.x = __float2bfloat16(o1.x); h2.y = __float2bfloat16(o1.y);
    __nv_bfloat162 h3; h3.x = __float2bfloat16(o1.z); h3.y = __float2bfloat16(o1.w);
    ((__nv_bfloat162*)(dr + lane*4))[0] = h0;
    ((__nv_bfloat162*)(dr + lane*4))[1] = h1;
    ((__nv_bfloat162*)(dr + 128 + lane*4))[0] = h2;
    ((__nv_bfloat162*)(dr + 128 + lane*4))[1] = h3;
}

// W -> [n][k] K-major bf16 (n<256: wk, else wv)
__global__ void prep_w_kernel(const float* __restrict__ wk, const float* __restrict__ wv,
                              __nv_bfloat16* __restrict__ B2)
{
    int n = blockIdx.x;
    int k = threadIdx.x;
    const float* W = (n < 256) ? wk : wv;
    B2[(size_t)n * 256 + k] = __float2bfloat16(W[(size_t)k * 256 + (n & 255)]);
}

// ---------------- K/V GEMM: pure bf16, 4 chunks of K=64 ----------------------
#define KV_SMEM (32768 * 2)
__global__ __launch_bounds__(256, 2)
void kv_gemm_mma(const __nv_bfloat16* __restrict__ A2, const __nv_bfloat16* __restrict__ B2,
                 const float* __restrict__ bk, const float* __restrict__ bv,
                 __nv_bfloat16* __restrict__ Kout, __nv_bfloat16* __restrict__ Vout)
{
    extern __shared__ char dsm[];
    uint32_t sbase = smem_u32(dsm);
    int tid = threadIdx.x, lane = tid & 31, wid = tid >> 5;
    int warp_m = wid & 1, warp_n = wid >> 1;
    int cb  = blockIdx.x;
    int m0  = blockIdx.y * 128;
    int mat = cb >> 1, nh = cb & 1;
    const float* bias = mat ? bv : bk;
    __nv_bfloat16* Out = mat ? Vout : Kout;

    float acc[4][4][4];
#pragma unroll
    for (int a = 0; a < 4; ++a)
#pragma unroll
        for (int b = 0; b < 4; ++b)
#pragma unroll
            for (int r = 0; r < 4; ++r) acc[a][b][r] = 0.0f;

    int lr = tid >> 3, lj = tid & 7;
    int brow_g = mat * 256 + nh * 128;

    int l7 = lane & 7, l15 = lane & 15, lhA = lane >> 4;
    int nrow_loc = (lane >> 4) * 8 + l7, hB = (lane >> 3) & 1;
    uint32_t aRow[4], bRow[2];
#pragma unroll
    for (int mt = 0; mt < 4; ++mt) aRow[mt] = (uint32_t)(warp_m*64 + mt*16 + l15) << 7;
#pragma unroll
    for (int g = 0; g < 2; ++g) bRow[g] = (uint32_t)(warp_n*32 + g*16 + nrow_loc) << 7;

#define LOAD_CHUNK(c, stg) do {                                               \
    uint32_t sa = sbase + (stg)*32768;                                        \
    int ko = (c)*64;                                                          \
    _Pragma("unroll")                                                         \
    for (int i = 0; i < 4; ++i) {                                             \
        int r = lr + i*32;                                                    \
        uint32_t so = (r<<7) + ((lj ^ (r&7))<<4);                             \
        cp_async16(sa + so, A2 + (size_t)(m0 + r)*256 + ko + lj*8);           \
        cp_async16(sa + 16384 + so, B2 + (size_t)(brow_g + r)*256 + ko + lj*8);\
    }                                                                         \
    CP_COMMIT();                                                              \
} while (0)

    LOAD_CHUNK(0, 0);
    LOAD_CHUNK(1, 1);

    for (int c = 0; c < 4; ++c) {
        if (c == 3) { CP_WAIT0(); } else { CP_WAIT1(); }
        __syncthreads();
        uint32_t sa = sbase + (c & 1) * 32768;
#pragma unroll
        for (int ks = 0; ks < 4; ++ks) {
            uint32_t achk = (uint32_t)(((2*ks + lhA) ^ l7) << 4);
            uint32_t bchk = (uint32_t)(((2*ks + hB)  ^ l7) << 4);
            uint32_t af[4][4], bf[2][4];
#pragma unroll
            for (int mt = 0; mt < 4; ++mt)
                LDMX4(af[mt][0], af[mt][1], af[mt][2], af[mt][3], sa + aRow[mt] + achk);
#pragma unroll
            for (int g = 0; g < 2; ++g)
                LDMX4(bf[g][0], bf[g][1], bf[g][2], bf[g][3], sa + 16384 + bRow[g] + bchk);
#pragma unroll
            for (int mt = 0; mt < 4; ++mt)
#pragma unroll
                for (int nt = 0; nt < 4; ++nt)
                    MMA16816(acc[mt][nt], af[mt][0], af[mt][1], af[mt][2], af[mt][3],
                             bf[nt>>1][(nt&1)*2], bf[nt>>1][(nt&1)*2+1]);
        }
        __syncthreads();
        if (c + 2 < 4) LOAD_CHUNK(c + 2, c & 1);
    }

    int col_base = nh * 128 + warp_n * 32;
    int h = col_base >> 5;
#pragma unroll
    for (int mt = 0; mt < 4; ++mt) {
#pragma unroll
        for (int half = 0; half < 2; ++half) {
            int m = m0 + warp_m * 64 + mt * 16 + (lane >> 2) + half * 8;
            int bi = m >> 12, nn = m & 4095;
            __nv_bfloat16* dst = Out + ((size_t)(bi * 8 + h) * 4096 + nn) * 32;
#pragma unroll
            for (int nt = 0; nt < 4; ++nt) {
                int dh = nt * 8 + (lane & 3) * 2;
                __nv_bfloat162 o;
                o.x = __float2bfloat16(acc[mt][nt][half*2+0] + bias[col_base + dh]);
                o.y = __float2bfloat16(acc[mt][nt][half*2+1] + bias[col_base + dh + 1]);
                *(__nv_bfloat162*)(dst + dh) = o;
            }
        }
    }
#undef LOAD_CHUNK
}

// ---------------- small GEMM (512 rows), optional fused input-LN -------------
// modes: 0 plain, 1 relu, 2 residual add, 3 q-layout remap,
//        4 virtual-A: A = (sum_c upd_part[c]) * inv_rs (resid = rs_part)
__global__ __launch_bounds__(256)
void gemm512_kernel(const float* __restrict__ Ain, const float* __restrict__ Win,
                    const float* __restrict__ biasin, float* __restrict__ outin,
                    int Ncols, int mode, const float* __restrict__ resid,
                    const float* __restrict__ lnw, const float* __restrict__ lnb,
                    const float* __restrict__ A2, const float* __restrict__ W2,
                    const float* __restrict__ bias2, float* __restrict__ out2,
                    int y2)
{
    __shared__ float As[64][36];
    __shared__ float Bs[64][68];
    __shared__ float s_mean[32], s_rstd[32];
    __shared__ float s_inv[256];
    int tid = threadIdx.x, tx = tid & 31, ty = tid >> 5;
    int c0 = tx*2, r0 = ty*4;
    int m0 = blockIdx.x * 32;
    int yb = blockIdx.y;
    const float* A = Ain; const float* W = Win; const float* bias = biasin;
    float* out = outin;
    if (yb >= y2) { A = A2; W = W2; bias = bias2; out = out2; yb -= y2; }
    int n0 = yb * 64;
    int do_ln = (lnw != nullptr);

    if (do_ln) {
        int r = ty * 4 + (tx >> 3);
        const float4* rp = (const float4*)(A + (size_t)(m0 + r) * 256);
        float s = 0.0f, sq = 0.0f;
        for (int j = (tx & 7); j < 64; j += 8) {
            float4 v = rp[j];
            s  += v.x + v.y + v.z + v.w;
            sq += v.x*v.x + v.y*v.y + v.z*v.z + v.w*v.w;
        }
#pragma unroll
        for (int o = 4; o > 0; o >>= 1) {
            s  += __shfl_xor_sync(~0u, s,  o);
            sq += __shfl_xor_sync(~0u, sq, o);
        }
        if ((tx & 7) == 0) {
            float mean = s * (1.0f/256.0f);
            s_mean[r] = mean;
            s_rstd[r] = rsqrtf(sq * (1.0f/256.0f) - mean*mean + LN_EPSc);
        }
    }
    if (mode == 4) {
        int r = tid >> 3, hh = tid & 7;
        int m = m0 + r, b = m >> 3, s = m & 7;
        int bh = b * 8 + hh;
        float t = resid[(size_t)(bh*4+0)*8 + s] + resid[(size_t)(bh*4+1)*8 + s]
                + resid[(size_t)(bh*4+2)*8 + s] + resid[(size_t)(bh*4+3)*8 + s];
        s_inv[r*8 + hh] = 1.0f / fmaxf(t, 1e-12f);
    }
    __syncthreads();

    float acc[4][2] = {};
    for (int kt = 0; kt < 4; ++kt) {
        __syncthreads();
#pragma unroll
        for (int i = 0; i < 2; ++i) {
            int fid = tid*2 + i, ar = fid >> 4, kq = fid & 15;
            float4 va;
            if (mode == 4) {
                int m = m0 + ar, b = m >> 3, s = m & 7;
                int c = kt*64 + kq*4;
                int h = c >> 5, cc = c & 31;
                size_t base = ((size_t)(b*8 + h) * 4) * 256 + s*32 + cc;
                float4 v0 = *(const float4*)(A + base);
                float4 v1 = *(const float4*)(A + base + 256);
                float4 v2 = *(const float4*)(A + base + 512);
                float4 v3 = *(const float4*)(A + base + 768);
                float iv = s_inv[ar*8 + h];
                va.x = (v0.x+v1.x+v2.x+v3.x)*iv;
                va.y = (v0.y+v1.y+v2.y+v3.y)*iv;
                va.z = (v0.z+v1.z+v2.z+v3.z)*iv;
                va.w = (v0.w+v1.w+v2.w+v3.w)*iv;
            } else {
                va = *(const float4*)(A + (size_t)(m0+ar)*256 + kt*64 + kq*4);
                if (do_ln) {
                    float mn = s_mean[ar], rs = s_rstd[ar];
                    float4 lw = *(const float4*)(lnw + kt*64 + kq*4);
                    float4 lb = *(const float4*)(lnb + kt*64 + kq*4);
                    va.x = (va.x - mn)*rs*lw.x + lb.x;
                    va.y = (va.y - mn)*rs*lw.y + lb.y;
                    va.z = (va.z - mn)*rs*lw.z + lb.z;
                    va.w = (va.w - mn)*rs*lw.w + lb.w;
                }
            }
            As[kq*4+0][ar]=va.x; As[kq*4+1][ar]=va.y; As[kq*4+2][ar]=va.z; As[kq*4+3][ar]=va.w;
        }
#pragma unroll
        for (int j = 0; j < 4; ++j) {
            int fid = tid + j*256, br = fid >> 4, c4 = fid & 15;
            *(float4*)&Bs[br][c4*4] = *(const float4*)(W + (size_t)(kt*64+br)*Ncols + n0 + c4*4);
        }
        __syncthreads();
#pragma unroll 8
        for (int k = 0; k < 64; ++k) {
            float4 a4 = *(const float4*)&As[k][r0];
            float2 b2 = *(const float2*)&Bs[k][c0];
            acc[0][0]+=a4.x*b2.x; acc[0][1]+=a4.x*b2.y;
            acc[1][0]+=a4.y*b2.x; acc[1][1]+=a4.y*b2.y;
            acc[2][0]+=a4.z*b2.x; acc[2][1]+=a4.z*b2.y;
            acc[3][0]+=a4.w*b2.x; acc[3][1]+=a4.w*b2.y;
        }
    }
#pragma unroll
    for (int i = 0; i < 4; ++i)
#pragma unroll
        for (int j = 0; j < 2; ++j) {
            int m = m0 + r0 + i, n = n0 + c0 + j;
            float v = acc[i][j] + bias[n];
            if (mode == 1)      out[(size_t)m*Ncols + n] = fmaxf(v, 0.0f);
            else if (mode == 2) out[(size_t)m*256 + n] = resid[(size_t)m*256 + n] + v;
            else if (mode == 3) {
                int bq = m >> 3, s = m & 7, h = n >> 5, dh = n & 31;
                out[((size_t)(bq*8 + h)*8 + s)*32 + dh] = v;
            }
            else                out[(size_t)m*Ncols + n] = v;  // modes 0, 4
        }
}

// ---------------- attention: MMA pass1 (QK^T), scalar pass2 -------------------
// attn_s stride 1028 (bank-conflict-free strided STS).
#define ATT_SMEM ((8224 + 256 + 64 + 2048) * sizeof(float))
__global__ __launch_bounds__(256)
void attention_part(const float* __restrict__ q, const __nv_bfloat16* __restrict__ Kh,
                    const __nv_bfloat16* __restrict__ Vh,
                    float* __restrict__ upd_part, float* __restrict__ rs_part,
                    float* __restrict__ attn_out, int write_attn)
{
    extern __shared__ float sm[];
    float* attn_s = sm;                   // [8][1028]
    float* q_s    = sm + 8224;            // [8][32]
    float* red    = q_s + 256;            // [8 warps][8]
    float* red2   = red + 64;             // [8][8][32]
    int bh = blockIdx.x, chunk = blockIdx.y;
    int tid = threadIdx.x, lane = tid & 31, wid = tid >> 5;
    int n0 = chunk * 1024;

    q_s[tid] = q[(size_t)bh*256 + tid] * 0.0625f;  // scale = D^-0.5 = 1/16
    __syncthreads();

    // build Q b-fragments (bf16): reg layout matches ldmatrix mats
    uint32_t qb[2][2];
    {
        int s = lane >> 2, kq = 2*(lane & 3);
#pragma unroll
        for (int ks = 0; ks < 2; ++ks) {
            __nv_bfloat162 p0, p1;
            p0.x = __float2bfloat16(q_s[s*32 + ks*16 + kq]);
            p0.y = __float2bfloat16(q_s[s*32 + ks*16 + kq + 1]);
            p1.x = __float2bfloat16(q_s[s*32 + ks*16 + 8 + kq]);
            p1.y = __float2bfloat16(q_s[s*32 + ks*16 + 8 + kq + 1]);
            qb[ks][0] = *(uint32_t*)&p0;
            qb[ks][1] = *(uint32_t*)&p1;
        }
    }

    // pass1: per warp 8 m-tiles of 16 n-rows; K A-frags direct from global
    float rs0 = 0.0f, rs1 = 0.0f;        // slots 2(l&3), 2(l&3)+1
    const __nv_bfloat16* Kb = Kh + (size_t)bh * 4096 * 32;
    int r = lane >> 2, kcol = 2*(lane & 3);
    int sl = kcol;                        // slot index base
    for (int mt = 0; mt < 8; ++mt) {
        int nb = n0 + wid*128 + mt*16;
        const __nv_bfloat16* kp  = Kb + (size_t)(nb + r) * 32 + kcol;
        const __nv_bfloat16* kp8 = kp + 8*32;
        float d[4] = {0.0f, 0.0f, 0.0f, 0.0f};
#pragma unroll
        for (int ks = 0; ks < 2; ++ks) {
            uint32_t a0 = *(const uint32_t*)(kp  + ks*16);
            uint32_t a1 = *(const uint32_t*)(kp8 + ks*16);
            uint32_t a2 = *(const uint32_t*)(kp  + ks*16 + 8);
            uint32_t a3 = *(const uint32_t*)(kp8 + ks*16 + 8);
            MMA16816(d, a0, a1, a2, a3, qb[ks][0], qb[ks][1]);
        }
        // softmax over 8 slots (within quad): rows r and r+8
        float ma = fmaxf(d[0], d[1]), mb = fmaxf(d[2], d[3]);
        ma = fmaxf(ma, __shfl_xor_sync(~0u, ma, 1));
        ma = fmaxf(ma, __shfl_xor_sync(~0u, ma, 2));
        mb = fmaxf(mb, __shfl_xor_sync(~0u, mb, 1));
        mb = fmaxf(mb, __shfl_xor_sync(~0u, mb, 2));
        float e0 = __expf(d[0]-ma), e1 = __expf(d[1]-ma);
        float e2 = __expf(d[2]-mb), e3 = __expf(d[3]-mb);
        float sa = e0 + e1, sb = e2 + e3;
        sa += __shfl_xor_sync(~0u, sa, 1); sa += __shfl_xor_sync(~0u, sa, 2);
        sb += __shfl_xor_sync(~0u, sb, 1); sb += __shfl_xor_sync(~0u, sb, 2);
        float ia = __fdividef(1.0f, sa), ib = __fdividef(1.0f, sb);
        float p0 = e0*ia + EPSc, p1 = e1*ia + EPSc;
        float p2 = e2*ib + EPSc, p3 = e3*ib + EPSc;
        int nl = wid*128 + mt*16 + r;
        attn_s[ sl   *1028 + nl]     = p0;
        attn_s[(sl+1)*1028 + nl]     = p1;
        attn_s[ sl   *1028 + nl + 8] = p2;
        attn_s[(sl+1)*1028 + nl + 8] = p3;
        rs0 += p0 + p2;
        rs1 += p1 + p3;
    }
    // reduce rs over lanes with same (l&3)
#pragma unroll
    for (int o = 16; o >= 4; o >>= 1) {
        rs0 += __shfl_xor_sync(~0u, rs0, o);
        rs1 += __shfl_xor_sync(~0u, rs1, o);
    }
    if (lane < 4) {
        red[wid*8 + 2*lane]     = rs0;
        red[wid*8 + 2*lane + 1] = rs1;
    }
    __syncthreads();
    if (tid < 8) {
        float t = 0.0f;
#pragma unroll
        for (int w = 0; w < 8; ++w) t += red[w*8 + tid];
        rs_part[(size_t)(bh*4 + chunk)*8 + tid] = t;
    }

    // pass2: warp w owns n-substripe [w*128, (w+1)*128) of this chunk
    {
        const __nv_bfloat16* Vb = Vh + (size_t)bh * 4096 * 32;
        float acc[8] = {};
        int nb = wid * 128;
        for (int nl = nb; nl < nb + 128; nl += 4) {
            float4 a[8];
#pragma unroll
            for (int s = 0; s < 8; ++s) a[s] = *(const float4*)(attn_s + s*1028 + nl);
            int n = n0 + nl;
            float v0 = __bfloat162float(Vb[(size_t)(n+0)*32 + lane]);
            float v1 = __bfloat162float(Vb[(size_t)(n+1)*32 + lane]);
            float v2 = __bfloat162float(Vb[(size_t)(n+2)*32 + lane]);
            float v3 = __bfloat162float(Vb[(size_t)(n+3)*32 + lane]);
#pragma unroll
            for (int s = 0; s < 8; ++s)
                acc[s] += a[s].x*v0 + a[s].y*v1 + a[s].z*v2 + a[s].w*v3;
        }
#pragma unroll
        for (int s = 0; s < 8; ++s) red2[(wid*8 + s)*32 + lane] = acc[s];
    }
    __syncthreads();
    {
        int s = tid >> 5, dh = tid & 31;
        float t = 0.0f;
#pragma unroll
        for (int w = 0; w < 8; ++w) t += red2[(w*8 + s)*32 + dh];
        upd_part[(size_t)(bh*4 + chunk)*256 + s*32 + dh] = t;
    }

    if (write_attn) {  // unnormalized p; scaled later by attn_scale
        float* ao = attn_out + (size_t)bh * 32768 + n0;
        for (int i = tid; i < 8192; i += 256)
            ao[(i >> 10) * 4096 + (i & 1023)] = attn_s[(i >> 10) * 1028 + (i & 1023)];
    }
}

__global__ void attn_scale(float* __restrict__ ao, const float* __restrict__ rsp)
{
    int bh = blockIdx.x, tid = threadIdx.x;
    __shared__ float inv[8];
    if (tid < 8) {
        float t = 0.0f;
#pragma unroll
        for (int c = 0; c < 4; ++c) t += rsp[(size_t)(bh*4 + c)*8 + tid];
        inv[tid] = 1.0f / fmaxf(t, 1e-12f);
    }
    __syncthreads();
    float* p = ao + (size_t)bh * 32768;
    for (int i = tid; i < 32768; i += 256)
        p[i] *= inv[i >> 12];
}

__global__ void gru_combine_kernel(const float* __restrict__ xg,
                                   const float* __restrict__ hg,
                                   float* __restrict__ slots)
{
    int idx = blockIdx.x * 256 + threadIdx.x;
    int row = idx >> 8, c = idx & 255;
    const float* x = xg + (size_t)row * 768;
    const float* h = hg + (size_t)row * 768;
    float r = 1.0f / (1.0f + expf(-(x[c]     + h[c])));
    float z = 1.0f / (1.0f + expf(-(x[256+c] + h[256+c])));
    float n = tanhf(x[512+c] + r * h[512+c]);
    slots[idx] = (1.0f - z) * n + z * slots[idx];
}

// ---------------- launcher ----------------------------------------------------
extern "C" void kernel_launch(void* const* d_in, const int* in_sizes, int n_in,
                              void* d_out, int out_size)
{
    const float* inp   = (const float*)d_in[0];
    const float* noise = (const float*)d_in[1];
    const float* smean = (const float*)d_in[2];
    const float* slogv = (const float*)d_in[3];
    const float* wq = (const float*)d_in[4];  const float* bq = (const float*)d_in[5];
    const float* wk = (const float*)d_in[6];  const float* bk = (const float*)d_in[7];
    const float* wv = (const float*)d_in[8];  const float* bv = (const float*)d_in[9];
    const float* wo = (const float*)d_in[10]; const float* bo = (const float*)d_in[11];
    const float* w_ih = (const float*)d_in[12]; const float* b_ih = (const float*)d_in[13];
    const float* w_hh = (const float*)d_in[14]; const float* b_hh = (const float*)d_in[15];
    const float* w1 = (const float*)d_in[16]; const float* b1 = (const float*)d_in[17];
    const float* w2 = (const float*)d_in[18]; const float* b2 = (const float*)d_in[19];
    const float* lin_w = (const float*)d_in[20]; const float* lin_b = (const float*)d_in[21];
    const float* ls_w  = (const float*)d_in[22]; const float* ls_b  = (const float*)d_in[23];
    const float* lff_w = (const float*)d_in[24]; const float* lff_b = (const float*)d_in[25];

    float* out      = (float*)d_out;
    float* attn_out = out + 131072;

    __nv_bfloat16 *a2, *wb2, *kbh, *vbh;
    float *slots,*qb,*upd2,*h1,*xg,*hg,*updp,*rsp;
    cudaGetSymbolAddress((void**)&a2,   g_a2);
    cudaGetSymbolAddress((void**)&wb2,  g_wb2);
    cudaGetSymbolAddress((void**)&kbh,  g_kbufh);
    cudaGetSymbolAddress((void**)&vbh,  g_vbufh);
    cudaGetSymbolAddress((void**)&slots,g_slots);
    cudaGetSymbolAddress((void**)&qb,   g_q);
    cudaGetSymbolAddress((void**)&upd2, g_upd2);
    cudaGetSymbolAddress((void**)&h1,   g_h1);
    cudaGetSymbolAddress((void**)&xg,   g_xg);
    cudaGetSymbolAddress((void**)&hg,   g_hg);
    cudaGetSymbolAddress((void**)&updp, g_updpart);
    cudaGetSymbolAddress((void**)&rsp,  g_rspart);

    cudaFuncSetAttribute(attention_part,
                         cudaFuncAttributeMaxDynamicSharedMemorySize, (int)ATT_SMEM);
    cudaFuncSetAttribute(kv_gemm_mma,
                         cudaFuncAttributeMaxDynamicSharedMemorySize, KV_SMEM);

    init_slots_kernel<<<BSc, 256>>>(noise, smean, slogv, slots);
    prep_w_kernel<<<512, 256>>>(wk, wv, wb2);
    ln_kv_kernel<<<Mc/8, 256>>>(inp, a2, lin_w, lin_b);
    kv_gemm_mma<<<dim3(4, Mc/128), 256, KV_SMEM>>>(a2, wb2, bk, bv, kbh, vbh);

    for (int it = 0; it < ITERS; ++it) {
        int last = (it == ITERS - 1);
        // q = LN(slots) @ wq (LN fused), remap to [B,H,S,DH]
        gemm512_kernel<<<dim3(16, 4), 256>>>(slots, wq, bq, qb, 256, 3, nullptr,
                                             ls_w, ls_b, nullptr, nullptr, nullptr, nullptr, 9999);
        attention_part<<<dim3(512, 4), 256, ATT_SMEM>>>(qb, kbh, vbh, updp, rsp, attn_out, last);
        // upd2 = (normalized upd from parts) @ wo + bo   (finalize fused, mode 4)
        gemm512_kernel<<<dim3(16, 4), 256>>>(updp, wo, bo, upd2, 256, 4, rsp,
                                             nullptr, nullptr, nullptr, nullptr, nullptr, nullptr, 9999);
        gemm512_kernel<<<dim3(16, 24), 256>>>(upd2, w_ih, b_ih, xg, 768, 0, nullptr,
                                              nullptr, nullptr, slots, w_hh, b_hh, hg, 12);
        gru_combine_kernel<<<BSc, 256>>>(xg, hg, slots);
        gemm512_kernel<<<dim3(16, 4), 256>>>(slots, w1, b1, h1, 256, 1, nullptr,
                                             lff_w, lff_b, nullptr, nullptr, nullptr, nullptr, 9999);
        gemm512_kernel<<<dim3(16, 4), 256>>>(h1, w2, b2, last ? out : slots, 256, 2, slots,
                                             nullptr, nullptr, nullptr, nullptr, nullptr, nullptr, 9999);
        if (last) attn_scale<<<512, 256>>>(attn_out, rsp);
    }
}